// round 9
// baseline (speedup 1.0000x reference)
#include <cuda_runtime.h>
#include <cstdint>

// FlowEmbedder cost, round 9: ONE-WAVE persistent grid (148 SM x 8 blocks x
// 128 thr) + software-pipelined grid-stride loop over float4 quads (2 pairs),
// prefetching next quad's loads under current compute. Math body = R6/R7:
// split forward-difference product chains, f32x2 packed, 0.08 folded into
// ex2 seeds, ISETP+SELP masks on the alu pipe. No reg cap (32-reg caps
// spilled in R5/R7).

typedef unsigned long long u64;

__device__ __forceinline__ u64 pk2(float lo, float hi) {
    u64 r; asm("mov.b64 %0, {%1, %2};" : "=l"(r) : "f"(lo), "f"(hi)); return r;
}
__device__ __forceinline__ void upk2(float& lo, float& hi, u64 v) {
    asm("mov.b64 {%0, %1}, %2;" : "=f"(lo), "=f"(hi) : "l"(v));
}
__device__ __forceinline__ u64 mul2(u64 a, u64 b) {
    u64 d; asm("mul.rn.f32x2 %0, %1, %2;" : "=l"(d) : "l"(a), "l"(b)); return d;
}
__device__ __forceinline__ u64 add2(u64 a, u64 b) {
    u64 d; asm("add.rn.f32x2 %0, %1, %2;" : "=l"(d) : "l"(a), "l"(b)); return d;
}
__device__ __forceinline__ u64 fma2(u64 a, u64 b, u64 c) {
    u64 d; asm("fma.rn.f32x2 %0, %1, %2, %3;" : "=l"(d) : "l"(a), "l"(b), "l"(c)); return d;
}
__device__ __forceinline__ u64 ex2_2(u64 g) {
    float a, b; upk2(a, b, g);
    asm("ex2.approx.f32 %0, %1;" : "=f"(a) : "f"(a));
    asm("ex2.approx.f32 %0, %1;" : "=f"(b) : "f"(b));
    return pk2(a, b);
}
__device__ __forceinline__ float rsq_ap(float x) {
    float r; asm("rsqrt.approx.f32 %0, %1;" : "=f"(r) : "f"(x)); return r;
}
// 1.0f iff s < n : ISETP + SELP on the alu pipe
__device__ __forceinline__ float imask(int s, int n) {
    float m;
    asm("{ .reg .pred p; setp.lt.s32 p, %1, %2;\n\t"
        "  selp.f32 %0, 0f3F800000, 0f00000000, p; }"
        : "=f"(m) : "r"(s), "r"(n));
    return m;
}

__device__ __forceinline__ void cost2(float ax0, float ay0, float bx0, float by0,
                                      float ax1, float ay1, float bx1, float by1,
                                      u64 P00, u64 P01, u64 P10, u64 P11,
                                      u64 P20, u64 P21,
                                      float& cost0, float& cost1) {
    // ---- scalar per-pair prologue -------------------------------------
    float dx0 = bx0 - ax0, dy0 = by0 - ay0;
    float dx1 = bx1 - ax1, dy1 = by1 - ay1;
    float d2_0 = fmaf(dx0, dx0, dy0 * dy0);
    float d2_1 = fmaf(dx1, dx1, dy1 * dy1);
    float euc0 = __fsqrt_rn(d2_0);
    float euc1 = __fsqrt_rn(d2_1);

    // correctly-rounded euc/0.1 (== __fdiv_rn, fl(1/0.1f)==10.0f exactly)
    float t0 = euc0 * 10.0f;
    float nf0 = floorf(fmaf(fmaf(-0.1f, t0, euc0), 10.0f, t0)) + 1.0f;
    float t1 = euc1 * 10.0f;
    float nf1 = floorf(fmaf(fmaf(-0.1f, t1, euc1), 10.0f, t1)) + 1.0f;
    int n0 = (int)nf0;
    int n1 = (int)nf1;

    float rs0 = rsq_ap(d2_0), rs1 = rsq_ap(d2_1);
    float h0 = (0.1f * dx0) * rs0, g0 = (0.1f * dy0) * rs0;
    float h1 = (0.1f * dx1) * rs1, g1 = (0.1f * dy1) * rs1;

    // ---- packed coefficient pipeline ----------------------------------
    u64 DX = pk2(dx0, dx1), DY = pk2(dy0, dy1);
    u64 X = pk2(ax0, ax1), Y = pk2(ay0, ay1);
    u64 H = pk2(h0, h1), G = pk2(g0, g1);

    u64 C0 = fma2(P01, DY, mul2(P00, DX));
    u64 C1 = fma2(P11, DY, mul2(P10, DX));
    u64 C2 = fma2(P21, DY, mul2(P20, DX));

    u64 XX = mul2(X, X), XY = mul2(X, Y), YY = mul2(Y, Y);
    u64 HH = mul2(H, H), HG = mul2(H, G), GG = mul2(G, G);
    u64 c2yy = mul2(C2, YY);
    u64 c2gg = mul2(C2, GG);

    u64 K0 = mul2(X, fma2(C0, XX, fma2(C1, XY, c2yy)));
    u64 K3 = mul2(H, fma2(C0, HH, fma2(C1, HG, c2gg)));

    u64 C0_3 = add2(C0, add2(C0, C0));
    u64 C1_2 = add2(C1, C1);
    u64 C2_2 = add2(C2, C2);

    u64 gx0 = fma2(C0_3, XX, fma2(C1_2, XY, c2yy));
    u64 gy0 = fma2(C1, XX, mul2(C2_2, XY));
    u64 K1 = fma2(G, gy0, mul2(H, gx0));
    u64 gx1 = fma2(C0_3, HH, fma2(C1_2, HG, c2gg));
    u64 gy1 = fma2(C1, HH, mul2(C2_2, HG));
    u64 K2 = fma2(Y, gy1, mul2(X, gx1));

    // ---- seeds (0.08 folded into E seeds) ------------------------------
    const u64 THREE2 = 0x4040000040400000ULL;  // {3,3}
    const u64 SIX2   = 0x40C0000040C00000ULL;  // {6,6}
    const u64 EIGHT2 = 0x4100000041000000ULL;  // {8,8}
    const u64 C17    = 0x4188000041880000ULL;  // {17,17}
    const u64 C217   = 0x4359000043590000ULL;  // {217,217}
    const u64 C54    = 0x4258000042580000ULL;  // {54,54}
    const u64 L2008  = 0xC0693574C0693574ULL;  // {log2(0.08), log2(0.08)}

    u64 DG  = add2(K1, add2(K2, K3));               // dg(0)
    u64 tt  = fma2(K3, THREE2, K2);
    u64 D2G = add2(tt, tt);                         // d2g(0)
    u64 W6  = mul2(K3, SIX2);                       // 6k3

    u64 G8   = fma2(fma2(fma2(K3, EIGHT2, K2), EIGHT2, K1), EIGHT2, K0);
    u64 DG8  = fma2(K2, C17, fma2(K3, C217, K1));   // dg(8)
    u64 D2G8 = fma2(K3, C54, add2(K2, K2));         // d2g(8)

    u64 EA = ex2_2(add2(K0, L2008));   // 0.08 * 2^{g(0)}
    u64 RA = ex2_2(DG);
    u64 QA = ex2_2(D2G);
    u64 W  = ex2_2(W6);
    u64 EB = ex2_2(add2(G8, L2008));   // 0.08 * 2^{g(8)}
    u64 RB = ex2_2(DG8);
    u64 QB = ex2_2(D2G8);

    // ---- two independent unrolled chains -------------------------------
    u64 accA = 0, accB = 0;
#pragma unroll
    for (int s = 0; s < 8; ++s) {
        u64 M = pk2(imask(s, n0), imask(s, n1));
        accA = fma2(EA, M, accA);
        if (s < 7) EA = mul2(EA, RA);
        if (s < 6) RA = mul2(RA, QA);
        if (s < 5) QA = mul2(QA, W);
    }
#pragma unroll
    for (int s = 8; s < 15; ++s) {
        u64 M = pk2(imask(s, n0), imask(s, n1));
        accB = fma2(EB, M, accB);
        if (s < 14) EB = mul2(EB, RB);
        if (s < 13) RB = mul2(RB, QB);
        if (s < 12) QB = mul2(QB, W);
    }

    u64 ACC = add2(accA, accB);
    float a0, a1;
    upk2(a0, a1, ACC);
    cost0 = fmaf(0.02f, nf0, a0);
    cost1 = fmaf(0.02f, nf1, a1);
}

__global__ void __launch_bounds__(128)
flow_cost_kernel(const float4* __restrict__ x1,
                 const float4* __restrict__ x2,
                 const float* __restrict__ pp,
                 float* __restrict__ out,
                 int n_pairs) {
    const float NL2E = -1.4426950408889634f;
    float p00 = NL2E * pp[0], p01 = NL2E * pp[1];
    float p10 = (3.0f * NL2E) * pp[2], p11 = (3.0f * NL2E) * pp[3];
    float p20 = (3.0f * NL2E) * pp[4], p21 = (3.0f * NL2E) * pp[5];
    u64 P00 = pk2(p00, p00), P01 = pk2(p01, p01);
    u64 P10 = pk2(p10, p10), P11 = pk2(p11, p11);
    u64 P20 = pk2(p20, p20), P21 = pk2(p21, p21);

    int tid = blockIdx.x * blockDim.x + threadIdx.x;
    int stride = gridDim.x * blockDim.x;
    int nquads = n_pairs >> 1;  // float4 units = 2 pairs each

    int j = tid;
    if (j < nquads) {
        float4 a = x1[j];
        float4 b = x2[j];
        for (;;) {
            int jn = j + stride;
            bool more = (jn < nquads);
            float4 an, bn;
            if (more) {        // prefetch next quad under current compute
                an = x1[jn];
                bn = x2[jn];
            }
            float c0, c1;
            cost2(a.x, a.y, b.x, b.y, a.z, a.w, b.z, b.w,
                  P00, P01, P10, P11, P20, P21, c0, c1);
            *reinterpret_cast<float2*>(out + 2 * j) = make_float2(c0, c1);
            if (!more) break;
            a = an; b = bn; j = jn;
        }
    }

    // odd tail pair (n_pairs odd): thread 0 handles it
    if ((n_pairs & 1) && tid == 0) {
        int p = n_pairs - 1;
        const float2* x1s = reinterpret_cast<const float2*>(x1);
        const float2* x2s = reinterpret_cast<const float2*>(x2);
        float2 a = x1s[p];
        float2 b = x2s[p];
        float c0, c1;
        cost2(a.x, a.y, b.x, b.y, a.x, a.y, b.x, b.y,
              P00, P01, P10, P11, P20, P21, c0, c1);
        out[p] = c0;
    }
}

extern "C" void kernel_launch(void* const* d_in, const int* in_sizes, int n_in,
                              void* d_out, int out_size) {
    const float4* x1 = (const float4*)d_in[0];
    const float4* x2 = (const float4*)d_in[1];
    const float*  pp = (const float*)d_in[2];
    float* out = (float*)d_out;

    int n_pairs = out_size;
    int threads = 128;
    int blocks = 148 * 8;  // one wave if regs <= 64 (expected ~48-56)
    flow_cost_kernel<<<blocks, threads>>>(x1, x2, pp, out, n_pairs);
}